// round 1
// baseline (speedup 1.0000x reference)
#include <cuda_runtime.h>

// Performer FAVOR+ (softmax kernel, non-causal) — fp32 baseline
// b=8,h=8,n=4096,d=64,m=256. out: [b,h,n,64] fp32.
//
// Pipeline:
//   init:    reset global-max accumulator
//   kdash:   k_dash = (norm*K)@P^T  -> scratch (256MB), global max (atomicMax mono-uint), k row diag
//   kctx:    k' = ratio*(exp(kdash - diag - kmax)+eps) on the fly; accumulate
//            partial context[m,e] and ksum[m] per n-chunk (deterministic partials)
//   reduce:  sum partials -> g_ctx, g_ksum
//   kq:      fused q side: q_dash GEMM -> rowmax/diag/exp in smem -> D=q'.ksum
//            -> out = (q' @ ctx) * (1/D)

static constexpr int BH = 64;     // b*h
static constexpr int Nn = 4096;
static constexpr int Dd = 64;
static constexpr int Mm = 256;
static constexpr int Ee = 64;
static constexpr int NS = 8;      // n-chunks for context partials
static constexpr float NORMALIZER = 0.35355339059327373f;  // 64^-0.25
static constexpr float RATIO = 0.0625f;                    // 256^-0.5
static constexpr float EPS_ = 1e-4f;

// ---- scratch (device globals; no allocation) ----
__device__ float    g_kdash[(size_t)BH * Nn * Mm];        // 256 MB
__device__ float    g_kdiag[BH * Nn];                     // 1 MB
__device__ unsigned g_kmax_u;                             // monotonic-mapped float max
__device__ float    g_ctx_part[(size_t)NS * BH * Mm * Ee];// 32 MB
__device__ float    g_ksum_part[NS * BH * Mm];
__device__ float    g_ctx[(size_t)BH * Mm * Ee];          // 4 MB
__device__ float    g_ksum[BH * Mm];

__device__ __forceinline__ unsigned f2mono(float x) {
    unsigned b = __float_as_uint(x);
    return (b & 0x80000000u) ? ~b : (b | 0x80000000u);
}
__device__ __forceinline__ float mono2f(unsigned u) {
    return __uint_as_float((u & 0x80000000u) ? (u & 0x7fffffffu) : ~u);
}

__global__ void init_kernel() { g_kmax_u = 0u; }

// ============================================================
// Kernel 1: k_dash = (norm*K) @ P^T, store + global max + k diag
// grid (N/64, BH), block (16,16)
// ============================================================
__global__ __launch_bounds__(256) void kdash_kernel(
    const float* __restrict__ K, const float* __restrict__ P)
{
    __shared__ float Ps[16 * 256];   // P chunk: [k-chunk(16)][m(256)]
    __shared__ float Ksm[64 * 65];   // K tile:  [row(64)][k(64)] padded, pre-scaled
    __shared__ float red[8];

    const int bh = blockIdx.y;
    const int n0 = blockIdx.x * 64;
    const int tx = threadIdx.x, ty = threadIdx.y;
    const int t = ty * 16 + tx;

    // Load K tile (scaled by normalizer): 4 threads per row, 16 floats each.
    {
        const float* Kb = K + ((size_t)bh * Nn + n0) * Dd;
        int r = t >> 2, c = (t & 3) * 16;
        #pragma unroll
        for (int j = 0; j < 16; j += 4) {
            float4 v = *(const float4*)(Kb + r * Dd + c + j);
            Ksm[r * 65 + c + j + 0] = v.x * NORMALIZER;
            Ksm[r * 65 + c + j + 1] = v.y * NORMALIZER;
            Ksm[r * 65 + c + j + 2] = v.z * NORMALIZER;
            Ksm[r * 65 + c + j + 3] = v.w * NORMALIZER;
        }
    }

    float acc[4][16];
    #pragma unroll
    for (int i = 0; i < 4; i++)
        #pragma unroll
        for (int j = 0; j < 16; j++) acc[i][j] = 0.f;

    for (int kc = 0; kc < Dd; kc += 16) {
        __syncthreads();   // also publishes Ksm on first iteration
        {   // load P chunk transposed: thread t handles column m=t
            const float* Pr = P + t * Dd + kc;
            #pragma unroll
            for (int kk = 0; kk < 16; kk += 4) {
                float4 v = *(const float4*)(Pr + kk);
                Ps[(kk + 0) * 256 + t] = v.x;
                Ps[(kk + 1) * 256 + t] = v.y;
                Ps[(kk + 2) * 256 + t] = v.z;
                Ps[(kk + 3) * 256 + t] = v.w;
            }
        }
        __syncthreads();
        #pragma unroll
        for (int kk = 0; kk < 16; kk++) {
            float a0 = Ksm[(ty * 4 + 0) * 65 + kc + kk];
            float a1 = Ksm[(ty * 4 + 1) * 65 + kc + kk];
            float a2 = Ksm[(ty * 4 + 2) * 65 + kc + kk];
            float a3 = Ksm[(ty * 4 + 3) * 65 + kc + kk];
            float b[16];
            #pragma unroll
            for (int j = 0; j < 16; j += 4) {
                float4 v = *(const float4*)&Ps[kk * 256 + tx * 16 + j];
                b[j] = v.x; b[j + 1] = v.y; b[j + 2] = v.z; b[j + 3] = v.w;
            }
            #pragma unroll
            for (int j = 0; j < 16; j++) {
                acc[0][j] = fmaf(a0, b[j], acc[0][j]);
                acc[1][j] = fmaf(a1, b[j], acc[1][j]);
                acc[2][j] = fmaf(a2, b[j], acc[2][j]);
                acc[3][j] = fmaf(a3, b[j], acc[3][j]);
            }
        }
    }

    // Store dash tile + local max
    float* op = g_kdash + ((size_t)bh * Nn + n0) * Mm;
    float mx = -3.4e38f;
    #pragma unroll
    for (int i = 0; i < 4; i++) {
        int row = ty * 4 + i;
        #pragma unroll
        for (int j = 0; j < 16; j += 4) {
            float4 v = make_float4(acc[i][j], acc[i][j + 1], acc[i][j + 2], acc[i][j + 3]);
            *(float4*)(op + (size_t)row * Mm + tx * 16 + j) = v;
            mx = fmaxf(mx, fmaxf(fmaxf(v.x, v.y), fmaxf(v.z, v.w)));
        }
    }
    #pragma unroll
    for (int o = 16; o > 0; o >>= 1)
        mx = fmaxf(mx, __shfl_xor_sync(0xffffffffu, mx, o));
    if ((t & 31) == 0) red[t >> 5] = mx;
    __syncthreads();
    if (t == 0) {
        float m2 = red[0];
        #pragma unroll
        for (int i = 1; i < 8; i++) m2 = fmaxf(m2, red[i]);
        atomicMax(&g_kmax_u, f2mono(m2));
    }
    // diag: Ksm is pre-scaled, so sum(Ksm^2) = norm^2 * ||k||^2; diag = 0.5 * that
    if (t < 64) {
        float s = 0.f;
        #pragma unroll
        for (int k = 0; k < Dd; k++) { float v = Ksm[t * 65 + k]; s = fmaf(v, v, s); }
        g_kdiag[bh * Nn + n0 + t] = 0.5f * s;
    }
}

// ============================================================
// Kernel 2: context partial [m,e] += k'[n,m]*v[n,e]; ksum partial
// grid (NS, BH), block (16,16): ty = m-group(16 rows), tx = e-group(4 cols)
// ============================================================
__global__ __launch_bounds__(256) void kctx_kernel(const float* __restrict__ V)
{
    __shared__ float kp[16 * 256];   // k' tile [n(16)][m(256)]
    __shared__ float vt[16 * 64];    // v  tile [n(16)][e(64)]

    const int chunk = blockIdx.x, bh = blockIdx.y;
    const int tx = threadIdx.x, ty = threadIdx.y;
    const int t = ty * 16 + tx;

    const float kmax = mono2f(g_kmax_u);
    const float* dash = g_kdash + (size_t)bh * Nn * Mm;
    const float* diag = g_kdiag + bh * Nn;
    const float* Vb = V + (size_t)bh * Nn * Ee;
    const int nbase = chunk * (Nn / NS);

    float acc[16][4];
    #pragma unroll
    for (int i = 0; i < 16; i++)
        #pragma unroll
        for (int j = 0; j < 4; j++) acc[i][j] = 0.f;
    float ksum_loc = 0.f;

    for (int nb = nbase; nb < nbase + (Nn / NS); nb += 16) {
        __syncthreads();
        // load + transform kdash -> k' ; thread t owns column m=t
        #pragma unroll
        for (int nn = 0; nn < 16; nn++) {
            float val = dash[(size_t)(nb + nn) * Mm + t];
            float e = RATIO * (__expf(val - diag[nb + nn] - kmax) + EPS_);
            kp[nn * 256 + t] = e;
            ksum_loc += e;
        }
        {   // load v tile: thread t -> row t>>4, 4 floats
            int nn = t >> 4, e0 = (t & 15) * 4;
            float4 v = *(const float4*)(Vb + (size_t)(nb + nn) * Ee + e0);
            vt[nn * 64 + e0 + 0] = v.x; vt[nn * 64 + e0 + 1] = v.y;
            vt[nn * 64 + e0 + 2] = v.z; vt[nn * 64 + e0 + 3] = v.w;
        }
        __syncthreads();
        #pragma unroll
        for (int nn = 0; nn < 16; nn++) {
            float4 b = *(const float4*)&vt[nn * 64 + tx * 4];
            float a[16];
            #pragma unroll
            for (int mi = 0; mi < 16; mi += 4) {
                float4 av = *(const float4*)&kp[nn * 256 + ty * 16 + mi];
                a[mi] = av.x; a[mi + 1] = av.y; a[mi + 2] = av.z; a[mi + 3] = av.w;
            }
            #pragma unroll
            for (int mi = 0; mi < 16; mi++) {
                acc[mi][0] = fmaf(a[mi], b.x, acc[mi][0]);
                acc[mi][1] = fmaf(a[mi], b.y, acc[mi][1]);
                acc[mi][2] = fmaf(a[mi], b.z, acc[mi][2]);
                acc[mi][3] = fmaf(a[mi], b.w, acc[mi][3]);
            }
        }
    }

    float* cp = g_ctx_part + ((size_t)chunk * BH + bh) * Mm * Ee;
    #pragma unroll
    for (int mi = 0; mi < 16; mi++) {
        int m = ty * 16 + mi;
        float4 v = make_float4(acc[mi][0], acc[mi][1], acc[mi][2], acc[mi][3]);
        *(float4*)(cp + (size_t)m * Ee + tx * 4) = v;
    }
    g_ksum_part[(size_t)chunk * BH * Mm + bh * Mm + t] = ksum_loc;
}

// ============================================================
// Kernel 2b: reduce NS partials -> g_ctx, g_ksum
// ============================================================
__global__ void reduce_kernel()
{
    const size_t CT = (size_t)BH * Mm * Ee;
    size_t idx = (size_t)blockIdx.x * 256 + threadIdx.x;
    if (idx < CT) {
        float s = 0.f;
        #pragma unroll
        for (int c = 0; c < NS; c++) s += g_ctx_part[(size_t)c * CT + idx];
        g_ctx[idx] = s;
    } else if (idx < CT + (size_t)BH * Mm) {
        size_t j = idx - CT;
        float s = 0.f;
        #pragma unroll
        for (int c = 0; c < NS; c++) s += g_ksum_part[(size_t)c * BH * Mm + j];
        g_ksum[j] = s;
    }
}

// ============================================================
// Kernel 3: fused q side.
// grid (N/64, BH), block (16,16), dynamic smem.
// ============================================================
static constexpr int SM3_FLOATS =
    16 * 256      // Ps
  + 64 * 65       // Qsm
  + 64 * 257      // qs (q_dash -> q'), padded pitch 257
  + 16 * 64       // cs (ctx chunk)
  + 256           // ksum_s
  + 64 + 64 + 64  // diag, stab, dinv
  + 64 * 4;       // Dpart
static constexpr size_t SM3_BYTES = (size_t)SM3_FLOATS * 4;

__global__ __launch_bounds__(256) void kq_kernel(
    const float* __restrict__ Q, const float* __restrict__ P,
    float* __restrict__ out)
{
    extern __shared__ float sm[];
    float* Ps    = sm;
    float* Qsm   = Ps + 16 * 256;
    float* qs    = Qsm + 64 * 65;
    float* cs    = qs + 64 * 257;
    float* ksum_s= cs + 16 * 64;
    float* diag  = ksum_s + 256;
    float* stab  = diag + 64;
    float* dinv  = stab + 64;
    float* Dpart = dinv + 64;

    const int bh = blockIdx.y;
    const int n0 = blockIdx.x * 64;
    const int tx = threadIdx.x, ty = threadIdx.y;
    const int t = ty * 16 + tx;

    {   // load Q tile (scaled)
        const float* Qb = Q + ((size_t)bh * Nn + n0) * Dd;
        int r = t >> 2, c = (t & 3) * 16;
        #pragma unroll
        for (int j = 0; j < 16; j += 4) {
            float4 v = *(const float4*)(Qb + r * Dd + c + j);
            Qsm[r * 65 + c + j + 0] = v.x * NORMALIZER;
            Qsm[r * 65 + c + j + 1] = v.y * NORMALIZER;
            Qsm[r * 65 + c + j + 2] = v.z * NORMALIZER;
            Qsm[r * 65 + c + j + 3] = v.w * NORMALIZER;
        }
    }
    ksum_s[t] = g_ksum[bh * Mm + t];

    // ---- GEMM: q_dash = Qsm @ P^T ----
    float acc[4][16];
    #pragma unroll
    for (int i = 0; i < 4; i++)
        #pragma unroll
        for (int j = 0; j < 16; j++) acc[i][j] = 0.f;

    for (int kc = 0; kc < Dd; kc += 16) {
        __syncthreads();
        {
            const float* Pr = P + t * Dd + kc;
            #pragma unroll
            for (int kk = 0; kk < 16; kk += 4) {
                float4 v = *(const float4*)(Pr + kk);
                Ps[(kk + 0) * 256 + t] = v.x;
                Ps[(kk + 1) * 256 + t] = v.y;
                Ps[(kk + 2) * 256 + t] = v.z;
                Ps[(kk + 3) * 256 + t] = v.w;
            }
        }
        __syncthreads();
        #pragma unroll
        for (int kk = 0; kk < 16; kk++) {
            float a0 = Qsm[(ty * 4 + 0) * 65 + kc + kk];
            float a1 = Qsm[(ty * 4 + 1) * 65 + kc + kk];
            float a2 = Qsm[(ty * 4 + 2) * 65 + kc + kk];
            float a3 = Qsm[(ty * 4 + 3) * 65 + kc + kk];
            float b[16];
            #pragma unroll
            for (int j = 0; j < 16; j += 4) {
                float4 v = *(const float4*)&Ps[kk * 256 + tx * 16 + j];
                b[j] = v.x; b[j + 1] = v.y; b[j + 2] = v.z; b[j + 3] = v.w;
            }
            #pragma unroll
            for (int j = 0; j < 16; j++) {
                acc[0][j] = fmaf(a0, b[j], acc[0][j]);
                acc[1][j] = fmaf(a1, b[j], acc[1][j]);
                acc[2][j] = fmaf(a2, b[j], acc[2][j]);
                acc[3][j] = fmaf(a3, b[j], acc[3][j]);
            }
        }
    }

    // dump dash to smem (padded pitch 257)
    #pragma unroll
    for (int i = 0; i < 4; i++) {
        int row = ty * 4 + i;
        #pragma unroll
        for (int j = 0; j < 16; j++) qs[row * 257 + tx * 16 + j] = acc[i][j];
    }
    __syncthreads();

    // per-row max + diag
    if (t < 64) {
        float mx = -3.4e38f;
        for (int m = 0; m < Mm; m++) mx = fmaxf(mx, qs[t * 257 + m]);
        stab[t] = mx;
        float s = 0.f;
        #pragma unroll
        for (int k = 0; k < Dd; k++) { float v = Qsm[t * 65 + k]; s = fmaf(v, v, s); }
        diag[t] = 0.5f * s;
    }
    __syncthreads();

    // transform to q' in place + partial D = q'.ksum
    {
        int r = t >> 2, c0 = (t & 3) * 64;
        float d = diag[r], st = stab[r];
        float D = 0.f;
        #pragma unroll 8
        for (int c = 0; c < 64; c++) {
            float val = RATIO * (__expf(qs[r * 257 + c0 + c] - d - st) + EPS_);
            qs[r * 257 + c0 + c] = val;
            D = fmaf(val, ksum_s[c0 + c], D);
        }
        Dpart[r * 4 + (t & 3)] = D;
    }
    __syncthreads();
    if (t < 64)
        dinv[t] = 1.f / (Dpart[t * 4] + Dpart[t * 4 + 1] + Dpart[t * 4 + 2] + Dpart[t * 4 + 3]);

    // ---- out = q' @ ctx ----
    float acc2[4][4];
    #pragma unroll
    for (int i = 0; i < 4; i++)
        #pragma unroll
        for (int j = 0; j < 4; j++) acc2[i][j] = 0.f;

    const float* ctx = g_ctx + (size_t)bh * Mm * Ee;
    for (int mc = 0; mc < Mm; mc += 16) {
        __syncthreads();
        {   // load ctx chunk [16m][64e]
            int mm = t >> 4, e0 = (t & 15) * 4;
            float4 v = *(const float4*)(ctx + (size_t)(mc + mm) * Ee + e0);
            cs[mm * 64 + e0 + 0] = v.x; cs[mm * 64 + e0 + 1] = v.y;
            cs[mm * 64 + e0 + 2] = v.z; cs[mm * 64 + e0 + 3] = v.w;
        }
        __syncthreads();
        #pragma unroll
        for (int mm = 0; mm < 16; mm++) {
            float4 b = *(const float4*)&cs[mm * 64 + tx * 4];
            float a0 = qs[(ty * 4 + 0) * 257 + mc + mm];
            float a1 = qs[(ty * 4 + 1) * 257 + mc + mm];
            float a2 = qs[(ty * 4 + 2) * 257 + mc + mm];
            float a3 = qs[(ty * 4 + 3) * 257 + mc + mm];
            acc2[0][0] = fmaf(a0, b.x, acc2[0][0]); acc2[0][1] = fmaf(a0, b.y, acc2[0][1]);
            acc2[0][2] = fmaf(a0, b.z, acc2[0][2]); acc2[0][3] = fmaf(a0, b.w, acc2[0][3]);
            acc2[1][0] = fmaf(a1, b.x, acc2[1][0]); acc2[1][1] = fmaf(a1, b.y, acc2[1][1]);
            acc2[1][2] = fmaf(a1, b.z, acc2[1][2]); acc2[1][3] = fmaf(a1, b.w, acc2[1][3]);
            acc2[2][0] = fmaf(a2, b.x, acc2[2][0]); acc2[2][1] = fmaf(a2, b.y, acc2[2][1]);
            acc2[2][2] = fmaf(a2, b.z, acc2[2][2]); acc2[2][3] = fmaf(a2, b.w, acc2[2][3]);
            acc2[3][0] = fmaf(a3, b.x, acc2[3][0]); acc2[3][1] = fmaf(a3, b.y, acc2[3][1]);
            acc2[3][2] = fmaf(a3, b.z, acc2[3][2]); acc2[3][3] = fmaf(a3, b.w, acc2[3][3]);
        }
    }

    #pragma unroll
    for (int i = 0; i < 4; i++) {
        int row = ty * 4 + i;
        float dv = dinv[row];
        float4 v = make_float4(acc2[i][0] * dv, acc2[i][1] * dv,
                               acc2[i][2] * dv, acc2[i][3] * dv);
        *(float4*)(out + ((size_t)bh * Nn + n0 + row) * Ee + tx * 4) = v;
    }
}

// ============================================================
extern "C" void kernel_launch(void* const* d_in, const int* in_sizes, int n_in,
                              void* d_out, int out_size)
{
    const float* q = (const float*)d_in[0];
    const float* k = (const float*)d_in[1];
    const float* v = (const float*)d_in[2];
    const float* p = (const float*)d_in[3];
    float* out = (float*)d_out;

    cudaFuncSetAttribute(kq_kernel, cudaFuncAttributeMaxDynamicSharedMemorySize,
                         (int)SM3_BYTES);

    dim3 blk(16, 16);
    init_kernel<<<1, 1>>>();
    kdash_kernel<<<dim3(Nn / 64, BH), blk>>>(k, p);
    kctx_kernel<<<dim3(NS, BH), blk>>>(v);
    size_t tot = (size_t)BH * Mm * Ee + (size_t)BH * Mm;
    reduce_kernel<<<(unsigned)((tot + 255) / 256), 256>>>();
    kq_kernel<<<dim3(Nn / 64, BH), blk, SM3_BYTES>>>(q, p, out);
    (void)in_sizes; (void)n_in; (void)out_size;
}

// round 2
// speedup vs baseline: 1.9326x; 1.9326x over previous
#include <cuda_runtime.h>
#include <cuda_bf16.h>

// Performer FAVOR+ — split-bf16 tensor-core version.
// b=8,h=8,n=4096,d=64,m=256. out: [b,h,n,64] fp32.
//
// All GEMMs run as 3-pass split-bf16 mma.sync (hi*hi + hi*lo + lo*hi),
// fp32 accumulate: effective per-term precision ~2^-17.
//
// Pipeline:
//   psplit:  P -> g_Phi/g_Plo bf16
//   init:    reset global max
//   kdash:   k_dash = (norm*K)@P^T -> g_kdash (fp32 scratch), global max, k diag
//   kctx:    k' = ratio*(exp(kdash - diag - kmax)+eps); partial ctx^T[e][m], ksum
//   reduce:  sum partials -> g_ctxThi/lo (bf16 split, [bh][e][m]), g_ksum
//   kq:      fused q side: dash GEMM -> rowmax/diag/exp -> D -> out GEMM -> /D

static constexpr int BH = 64;
static constexpr int Nn = 4096;
static constexpr int Dd = 64;
static constexpr int Mm = 256;
static constexpr int Ee = 64;
static constexpr int NS = 16;     // n-chunks for ctx partials
static constexpr float NORMALIZER = 0.35355339059327373f;  // 64^-0.25
static constexpr float RATIO = 0.0625f;                    // 256^-0.5
static constexpr float EPS_ = 1e-4f;

// ---- device scratch ----
__device__ float    g_kdash[(size_t)BH * Nn * Mm];          // 256 MB
__device__ float    g_kdiag[BH * Nn];
__device__ unsigned g_kmax_u;
__device__ float    g_ctx_part[(size_t)NS * BH * Ee * Mm];  // 64 MB, [c][bh][e][m]
__device__ float    g_ksum_part[NS * BH * Mm];
__device__ float    g_ksum[BH * Mm];
__device__ __align__(16) __nv_bfloat16 g_Phi[Mm * Dd];
__device__ __align__(16) __nv_bfloat16 g_Plo[Mm * Dd];
__device__ __align__(16) __nv_bfloat16 g_ctxThi[BH * Ee * Mm];  // [bh][e][m]
__device__ __align__(16) __nv_bfloat16 g_ctxTlo[BH * Ee * Mm];

__device__ __forceinline__ unsigned f2mono(float x) {
    unsigned b = __float_as_uint(x);
    return (b & 0x80000000u) ? ~b : (b | 0x80000000u);
}
__device__ __forceinline__ float mono2f(unsigned u) {
    return __uint_as_float((u & 0x80000000u) ? (u & 0x7fffffffu) : ~u);
}
__device__ __forceinline__ void splitbf(float a, __nv_bfloat16& h, __nv_bfloat16& l) {
    h = __float2bfloat16(a);
    l = __float2bfloat16(a - __bfloat162float(h));
}
__device__ __forceinline__ void mma16816(float c[4],
    unsigned a0, unsigned a1, unsigned a2, unsigned a3, unsigned b0, unsigned b1) {
    asm volatile(
        "mma.sync.aligned.m16n8k16.row.col.f32.bf16.bf16.f32 "
        "{%0,%1,%2,%3},{%4,%5,%6,%7},{%8,%9},{%0,%1,%2,%3};"
        : "+f"(c[0]), "+f"(c[1]), "+f"(c[2]), "+f"(c[3])
        : "r"(a0), "r"(a1), "r"(a2), "r"(a3), "r"(b0), "r"(b1));
}

__global__ void init_kernel() { g_kmax_u = 0u; }

__global__ void psplit_kernel(const float* __restrict__ P) {
    int i = blockIdx.x * 256 + threadIdx.x;   // 16384 total
    __nv_bfloat16 h, l;
    splitbf(P[i], h, l);
    g_Phi[i] = h;
    g_Plo[i] = l;
}

// ============================================================
// kdash: dash tile [128 n][128 m] per block; grid (32, 2, 64)
// ============================================================
static constexpr int PIT = 68;   // smem pitch in bf16 elems (even, conflict-spread)
static constexpr size_t KD_SMEM = (size_t)4 * 128 * PIT * sizeof(__nv_bfloat16);

__global__ __launch_bounds__(256) void kdash_kernel(const float* __restrict__ K)
{
    extern __shared__ __nv_bfloat16 smk[];
    __nv_bfloat16* Ahi = smk;
    __nv_bfloat16* Alo = Ahi + 128 * PIT;
    __nv_bfloat16* Bhi = Alo + 128 * PIT;
    __nv_bfloat16* Blo = Bhi + 128 * PIT;
    __shared__ float redmax[8];

    const int bh = blockIdx.z, n0 = blockIdx.x * 128, m0 = blockIdx.y * 128;
    const int t = threadIdx.x, lane = t & 31, wid = t >> 5;

    // A = norm*K tile [128][64] -> split bf16; row sumsq -> diag
    {
        const float* Kb = K + ((size_t)bh * Nn + n0) * Dd;
        int row = t >> 1, half = t & 1, c0 = half * 32;
        float ss = 0.f;
        #pragma unroll
        for (int j = 0; j < 32; j += 4) {
            float4 v = *(const float4*)(Kb + (size_t)row * Dd + c0 + j);
            float a[4] = {v.x * NORMALIZER, v.y * NORMALIZER,
                          v.z * NORMALIZER, v.w * NORMALIZER};
            #pragma unroll
            for (int u = 0; u < 4; u++) {
                float x = a[u];
                ss = fmaf(x, x, ss);
                __nv_bfloat16 h, l;
                splitbf(x, h, l);
                Ahi[row * PIT + c0 + j + u] = h;
                Alo[row * PIT + c0 + j + u] = l;
            }
        }
        ss += __shfl_xor_sync(0xffffffffu, ss, 1);
        if (half == 0 && m0 == 0) g_kdiag[bh * Nn + n0 + row] = 0.5f * ss;
    }
    // B = pre-split P tile [128 m][64]
    {
        const uint2* sh = (const uint2*)(g_Phi + (size_t)m0 * Dd);
        const uint2* sl = (const uint2*)(g_Plo + (size_t)m0 * Dd);
        #pragma unroll
        for (int j = 0; j < 8; j++) {
            int cid = t * 8 + j;                 // 2048 uint2
            int row = cid >> 4, c4 = (cid & 15) * 4;
            *(uint2*)&Bhi[row * PIT + c4] = sh[cid];
            *(uint2*)&Blo[row * PIT + c4] = sl[cid];
        }
    }
    __syncthreads();

    const int warp_m = wid >> 1, warp_n = wid & 1;
    const int g = lane >> 2, tig = lane & 3;
    float c[2][8][4];
    #pragma unroll
    for (int i = 0; i < 2; i++)
        #pragma unroll
        for (int j = 0; j < 8; j++)
            #pragma unroll
            for (int u = 0; u < 4; u++) c[i][j][u] = 0.f;

    #pragma unroll
    for (int kk = 0; kk < 4; kk++) {
        const int cA = kk * 16 + 2 * tig;
        unsigned ah[2][4], al[2][4];
        #pragma unroll
        for (int i = 0; i < 2; i++) {
            int r0 = warp_m * 32 + i * 16 + g;
            ah[i][0] = *(const unsigned*)&Ahi[r0 * PIT + cA];
            ah[i][1] = *(const unsigned*)&Ahi[(r0 + 8) * PIT + cA];
            ah[i][2] = *(const unsigned*)&Ahi[r0 * PIT + cA + 8];
            ah[i][3] = *(const unsigned*)&Ahi[(r0 + 8) * PIT + cA + 8];
            al[i][0] = *(const unsigned*)&Alo[r0 * PIT + cA];
            al[i][1] = *(const unsigned*)&Alo[(r0 + 8) * PIT + cA];
            al[i][2] = *(const unsigned*)&Alo[r0 * PIT + cA + 8];
            al[i][3] = *(const unsigned*)&Alo[(r0 + 8) * PIT + cA + 8];
        }
        #pragma unroll
        for (int j = 0; j < 8; j++) {
            int nr = warp_n * 64 + j * 8 + g;
            unsigned b0 = *(const unsigned*)&Bhi[nr * PIT + cA];
            unsigned b1 = *(const unsigned*)&Bhi[nr * PIT + cA + 8];
            unsigned l0 = *(const unsigned*)&Blo[nr * PIT + cA];
            unsigned l1 = *(const unsigned*)&Blo[nr * PIT + cA + 8];
            #pragma unroll
            for (int i = 0; i < 2; i++) {
                mma16816(c[i][j], ah[i][0], ah[i][1], ah[i][2], ah[i][3], b0, b1);
                mma16816(c[i][j], ah[i][0], ah[i][1], ah[i][2], ah[i][3], l0, l1);
                mma16816(c[i][j], al[i][0], al[i][1], al[i][2], al[i][3], b0, b1);
            }
        }
    }

    // store dash + block max
    float mx = -3.4e38f;
    float* op = g_kdash + ((size_t)bh * Nn + n0) * Mm + m0;
    #pragma unroll
    for (int i = 0; i < 2; i++) {
        int row = warp_m * 32 + i * 16 + g;
        #pragma unroll
        for (int j = 0; j < 8; j++) {
            int col = warp_n * 64 + j * 8 + 2 * tig;
            float2 v0 = make_float2(c[i][j][0], c[i][j][1]);
            float2 v1 = make_float2(c[i][j][2], c[i][j][3]);
            *(float2*)(op + (size_t)row * Mm + col) = v0;
            *(float2*)(op + (size_t)(row + 8) * Mm + col) = v1;
            mx = fmaxf(mx, fmaxf(fmaxf(v0.x, v0.y), fmaxf(v1.x, v1.y)));
        }
    }
    #pragma unroll
    for (int o = 16; o > 0; o >>= 1)
        mx = fmaxf(mx, __shfl_xor_sync(0xffffffffu, mx, o));
    if (lane == 0) redmax[wid] = mx;
    __syncthreads();
    if (t == 0) {
        float m2 = redmax[0];
        #pragma unroll
        for (int i = 1; i < 8; i++) m2 = fmaxf(m2, redmax[i]);
        atomicMax(&g_kmax_u, f2mono(m2));
    }
}

// ============================================================
// kctx: ctx^T partial [64 e][256 m] over 256-n chunk; grid (NS, BH)
// ============================================================
static constexpr int KP = 36;

__global__ __launch_bounds__(256) void kctx_kernel(const float* __restrict__ V)
{
    __shared__ __nv_bfloat16 Khi[256 * KP], Klo[256 * KP];
    __shared__ __nv_bfloat16 Vhi[64 * KP], Vlo[64 * KP];

    const int chunk = blockIdx.x, bh = blockIdx.y;
    const int t = threadIdx.x, lane = t & 31, wid = t >> 5;
    const int g = lane >> 2, tig = lane & 3;

    const float kmax = mono2f(g_kmax_u);
    const float* dash = g_kdash + (size_t)bh * Nn * Mm;
    const float* diag = g_kdiag + bh * Nn;
    const float* Vb = V + (size_t)bh * Nn * Ee;
    const int nbase = chunk * (Nn / NS);   // 256 n per block

    float c[2][8][4];
    #pragma unroll
    for (int i = 0; i < 2; i++)
        #pragma unroll
        for (int j = 0; j < 8; j++)
            #pragma unroll
            for (int u = 0; u < 4; u++) c[i][j][u] = 0.f;
    float ksum_loc = 0.f;

    for (int r = 0; r < 8; r++) {          // rounds of 32 n
        const int n0 = nbase + r * 32;
        __syncthreads();
        // transform: thread t owns m=t
        #pragma unroll 4
        for (int nn = 0; nn < 32; nn++) {
            float val = dash[(size_t)(n0 + nn) * Mm + t];
            float e = RATIO * (__expf(val - diag[n0 + nn] - kmax) + EPS_);
            ksum_loc += e;
            __nv_bfloat16 h, l;
            splitbf(e, h, l);
            Khi[t * KP + nn] = h;
            Klo[t * KP + nn] = l;
        }
        // v transpose+split: [e][n]
        {
            int nl = t >> 3, e0 = (t & 7) * 8;
            const float* vr = Vb + (size_t)(n0 + nl) * Ee + e0;
            #pragma unroll
            for (int u = 0; u < 8; u++) {
                __nv_bfloat16 h, l;
                splitbf(vr[u], h, l);
                Vhi[(e0 + u) * KP + nl] = h;
                Vlo[(e0 + u) * KP + nl] = l;
            }
        }
        __syncthreads();
        #pragma unroll
        for (int kk = 0; kk < 2; kk++) {
            const int cA = kk * 16 + 2 * tig;
            unsigned ah[2][4], al[2][4];
            #pragma unroll
            for (int i = 0; i < 2; i++) {
                int r0 = wid * 32 + i * 16 + g;
                ah[i][0] = *(const unsigned*)&Khi[r0 * KP + cA];
                ah[i][1] = *(const unsigned*)&Khi[(r0 + 8) * KP + cA];
                ah[i][2] = *(const unsigned*)&Khi[r0 * KP + cA + 8];
                ah[i][3] = *(const unsigned*)&Khi[(r0 + 8) * KP + cA + 8];
                al[i][0] = *(const unsigned*)&Klo[r0 * KP + cA];
                al[i][1] = *(const unsigned*)&Klo[(r0 + 8) * KP + cA];
                al[i][2] = *(const unsigned*)&Klo[r0 * KP + cA + 8];
                al[i][3] = *(const unsigned*)&Klo[(r0 + 8) * KP + cA + 8];
            }
            #pragma unroll
            for (int j = 0; j < 8; j++) {
                int er = j * 8 + g;
                unsigned b0 = *(const unsigned*)&Vhi[er * KP + cA];
                unsigned b1 = *(const unsigned*)&Vhi[er * KP + cA + 8];
                unsigned l0 = *(const unsigned*)&Vlo[er * KP + cA];
                unsigned l1 = *(const unsigned*)&Vlo[er * KP + cA + 8];
                #pragma unroll
                for (int i = 0; i < 2; i++) {
                    mma16816(c[i][j], ah[i][0], ah[i][1], ah[i][2], ah[i][3], b0, b1);
                    mma16816(c[i][j], ah[i][0], ah[i][1], ah[i][2], ah[i][3], l0, l1);
                    mma16816(c[i][j], al[i][0], al[i][1], al[i][2], al[i][3], b0, b1);
                }
            }
        }
    }

    // epilogue: partial ctx^T [e][m]
    float* cp = g_ctx_part + ((size_t)chunk * BH + bh) * Ee * Mm;
    #pragma unroll
    for (int i = 0; i < 2; i++) {
        int m = wid * 32 + i * 16 + g;
        #pragma unroll
        for (int j = 0; j < 8; j++) {
            int e = j * 8 + 2 * tig;
            cp[(size_t)e * Mm + m]           = c[i][j][0];
            cp[(size_t)(e + 1) * Mm + m]     = c[i][j][1];
            cp[(size_t)e * Mm + m + 8]       = c[i][j][2];
            cp[(size_t)(e + 1) * Mm + m + 8] = c[i][j][3];
        }
    }
    g_ksum_part[((size_t)chunk * BH + bh) * Mm + t] = ksum_loc;
}

// ============================================================
// reduce: sum NS partials -> g_ctxThi/lo (bf16 split), g_ksum
// ============================================================
__global__ void reduce_kernel()
{
    const int CT = BH * Ee * Mm;   // 1048576
    int idx = blockIdx.x * 256 + threadIdx.x;
    if (idx < CT) {
        float s = 0.f;
        #pragma unroll
        for (int cI = 0; cI < NS; cI++)
            s += g_ctx_part[(size_t)cI * CT + idx];
        __nv_bfloat16 h, l;
        splitbf(s, h, l);
        g_ctxThi[idx] = h;
        g_ctxTlo[idx] = l;
    } else if (idx < CT + BH * Mm) {
        int j = idx - CT;
        float s = 0.f;
        #pragma unroll
        for (int cI = 0; cI < NS; cI++)
            s += g_ksum_part[(size_t)cI * BH * Mm + j];
        g_ksum[j] = s;
    }
}

// ============================================================
// kq: fused q side, tile 64 n-rows per block; grid (64, BH)
// ============================================================
static constexpr size_t KQ_SMEM =
    (size_t)(64 * PIT * 2 + 128 * PIT * 2) * sizeof(__nv_bfloat16)  // Q hi/lo, P hi/lo
  + (size_t)(64 * 260 + 256 + 64 * 3 + 256) * sizeof(float);        // qs, ksum, diag/stab/dinv, part

__global__ __launch_bounds__(256) void kq_kernel(
    const float* __restrict__ Q, float* __restrict__ out)
{
    extern __shared__ char smraw[];
    __nv_bfloat16* Qhi = (__nv_bfloat16*)smraw;
    __nv_bfloat16* Qlo = Qhi + 64 * PIT;
    __nv_bfloat16* PA  = Qlo + 64 * PIT;        // 128*PIT (hi)  -> reused qphi/qplo
    __nv_bfloat16* PB  = PA + 128 * PIT;        // 128*PIT (lo)  -> reused cthi/ctlo
    float* qs     = (float*)(PB + 128 * PIT);   // [64][260]
    float* ksum_s = qs + 64 * 260;
    float* diag   = ksum_s + 256;
    float* stab   = diag + 64;
    float* dinv   = stab + 64;
    float* part   = dinv + 64;                  // [256]

    const int bh = blockIdx.y, n0 = blockIdx.x * 64;
    const int t = threadIdx.x, lane = t & 31, wid = t >> 5;
    const int g = lane >> 2, tig = lane & 3;
    const int warp_m = wid >> 2, warp_n = wid & 3;

    // Q load+scale+split + diag
    {
        const float* Qb = Q + ((size_t)bh * Nn + n0) * Dd;
        int row = t >> 2, qd = t & 3, c0 = qd * 16;
        float ss = 0.f;
        #pragma unroll
        for (int j = 0; j < 16; j += 4) {
            float4 v = *(const float4*)(Qb + (size_t)row * Dd + c0 + j);
            float a[4] = {v.x * NORMALIZER, v.y * NORMALIZER,
                          v.z * NORMALIZER, v.w * NORMALIZER};
            #pragma unroll
            for (int u = 0; u < 4; u++) {
                float x = a[u];
                ss = fmaf(x, x, ss);
                __nv_bfloat16 h, l;
                splitbf(x, h, l);
                Qhi[row * PIT + c0 + j + u] = h;
                Qlo[row * PIT + c0 + j + u] = l;
            }
        }
        ss += __shfl_xor_sync(0xffffffffu, ss, 1);
        ss += __shfl_xor_sync(0xffffffffu, ss, 2);
        if (qd == 0) diag[row] = 0.5f * ss;
        ksum_s[t] = g_ksum[bh * Mm + t];
    }

    // GEMM1: dash = Q' @ P^T in two m-halves of 128
    for (int hlf = 0; hlf < 2; hlf++) {
        const int m0 = hlf * 128;
        __syncthreads();
        {
            const uint2* sh = (const uint2*)(g_Phi + (size_t)m0 * Dd);
            const uint2* sl = (const uint2*)(g_Plo + (size_t)m0 * Dd);
            #pragma unroll
            for (int j = 0; j < 8; j++) {
                int cid = t * 8 + j;
                int row = cid >> 4, c4 = (cid & 15) * 4;
                *(uint2*)&PA[row * PIT + c4] = sh[cid];
                *(uint2*)&PB[row * PIT + c4] = sl[cid];
            }
        }
        __syncthreads();

        float c[2][4][4];
        #pragma unroll
        for (int i = 0; i < 2; i++)
            #pragma unroll
            for (int j = 0; j < 4; j++)
                #pragma unroll
                for (int u = 0; u < 4; u++) c[i][j][u] = 0.f;

        #pragma unroll
        for (int kk = 0; kk < 4; kk++) {
            const int cA = kk * 16 + 2 * tig;
            unsigned ah[2][4], al[2][4];
            #pragma unroll
            for (int i = 0; i < 2; i++) {
                int r0 = warp_m * 32 + i * 16 + g;
                ah[i][0] = *(const unsigned*)&Qhi[r0 * PIT + cA];
                ah[i][1] = *(const unsigned*)&Qhi[(r0 + 8) * PIT + cA];
                ah[i][2] = *(const unsigned*)&Qhi[r0 * PIT + cA + 8];
                ah[i][3] = *(const unsigned*)&Qhi[(r0 + 8) * PIT + cA + 8];
                al[i][0] = *(const unsigned*)&Qlo[r0 * PIT + cA];
                al[i][1] = *(const unsigned*)&Qlo[(r0 + 8) * PIT + cA];
                al[i][2] = *(const unsigned*)&Qlo[r0 * PIT + cA + 8];
                al[i][3] = *(const unsigned*)&Qlo[(r0 + 8) * PIT + cA + 8];
            }
            #pragma unroll
            for (int j = 0; j < 4; j++) {
                int nr = warp_n * 32 + j * 8 + g;
                unsigned b0 = *(const unsigned*)&PA[nr * PIT + cA];
                unsigned b1 = *(const unsigned*)&PA[nr * PIT + cA + 8];
                unsigned l0 = *(const unsigned*)&PB[nr * PIT + cA];
                unsigned l1 = *(const unsigned*)&PB[nr * PIT + cA + 8];
                #pragma unroll
                for (int i = 0; i < 2; i++) {
                    mma16816(c[i][j], ah[i][0], ah[i][1], ah[i][2], ah[i][3], b0, b1);
                    mma16816(c[i][j], ah[i][0], ah[i][1], ah[i][2], ah[i][3], l0, l1);
                    mma16816(c[i][j], al[i][0], al[i][1], al[i][2], al[i][3], b0, b1);
                }
            }
        }
        // dump dash half to qs
        #pragma unroll
        for (int i = 0; i < 2; i++) {
            int row = warp_m * 32 + i * 16 + g;
            #pragma unroll
            for (int j = 0; j < 4; j++) {
                int col = m0 + warp_n * 32 + j * 8 + 2 * tig;
                qs[row * 260 + col]       = c[i][j][0];
                qs[row * 260 + col + 1]   = c[i][j][1];
                qs[(row + 8) * 260 + col]     = c[i][j][2];
                qs[(row + 8) * 260 + col + 1] = c[i][j][3];
            }
        }
    }
    __syncthreads();

    // row max (4 threads per row)
    {
        int row = t >> 2, qd = t & 3;
        float mx = -3.4e38f;
        #pragma unroll 8
        for (int i = 0; i < 64; i++) mx = fmaxf(mx, qs[row * 260 + qd * 64 + i]);
        part[t] = mx;
    }
    __syncthreads();
    if (t < 64)
        stab[t] = fmaxf(fmaxf(part[t * 4], part[t * 4 + 1]),
                        fmaxf(part[t * 4 + 2], part[t * 4 + 3]));
    __syncthreads();

    // transform to q' + D partial
    {
        int row = t >> 2, qd = t & 3;
        float d = diag[row], st = stab[row], D = 0.f;
        #pragma unroll 8
        for (int i = 0; i < 64; i++) {
            int col = qd * 64 + i;
            float e = RATIO * (__expf(qs[row * 260 + col] - d - st) + EPS_);
            qs[row * 260 + col] = e;
            D = fmaf(e, ksum_s[col], D);
        }
        part[t] = D;
    }
    __syncthreads();
    if (t < 64)
        dinv[t] = 1.f / (part[t * 4] + part[t * 4 + 1] + part[t * 4 + 2] + part[t * 4 + 3]);

    // GEMM2: out = q' @ ctx, loop 4 m-chunks of 64, accumulate
    __nv_bfloat16* qphi = PA;
    __nv_bfloat16* qplo = PA + 64 * PIT;
    __nv_bfloat16* cthi = PB;
    __nv_bfloat16* ctlo = PB + 64 * PIT;

    float c2[2][2][4];
    #pragma unroll
    for (int i = 0; i < 2; i++)
        #pragma unroll
        for (int j = 0; j < 2; j++)
            #pragma unroll
            for (int u = 0; u < 4; u++) c2[i][j][u] = 0.f;

    for (int mc = 0; mc < 4; mc++) {
        __syncthreads();
        // split q' chunk [64 rows][64 m]
        {
            int row = t >> 2, qd = t & 3;
            #pragma unroll
            for (int i = 0; i < 16; i++) {
                int col = qd * 16 + i;
                __nv_bfloat16 h, l;
                splitbf(qs[row * 260 + mc * 64 + col], h, l);
                qphi[row * PIT + col] = h;
                qplo[row * PIT + col] = l;
            }
        }
        // load ctx^T chunk [64 e][64 m] (pre-split bf16)
        {
            const __nv_bfloat16* sh = g_ctxThi + (size_t)bh * Ee * Mm + mc * 64;
            const __nv_bfloat16* sl = g_ctxTlo + (size_t)bh * Ee * Mm + mc * 64;
            #pragma unroll
            for (int j = 0; j < 4; j++) {
                int cid = t * 4 + j;            // 1024 uint2
                int e = cid >> 4, c4 = (cid & 15) * 4;
                *(uint2*)&cthi[e * PIT + c4] = *(const uint2*)(sh + (size_t)e * Mm + c4);
                *(uint2*)&ctlo[e * PIT + c4] = *(const uint2*)(sl + (size_t)e * Mm + c4);
            }
        }
        __syncthreads();
        #pragma unroll
        for (int kk = 0; kk < 4; kk++) {
            const int cA = kk * 16 + 2 * tig;
            unsigned ah[2][4], al[2][4];
            #pragma unroll
            for (int i = 0; i < 2; i++) {
                int r0 = warp_m * 32 + i * 16 + g;
                ah[i][0] = *(const unsigned*)&qphi[r0 * PIT + cA];
                ah[i][1] = *(const unsigned*)&qphi[(r0 + 8) * PIT + cA];
                ah[i][2] = *(const unsigned*)&qphi[r0 * PIT + cA + 8];
                ah[i][3] = *(const unsigned*)&qphi[(r0 + 8) * PIT + cA + 8];
                al[i][0] = *(const unsigned*)&qplo[r0 * PIT + cA];
                al[i][1] = *(const unsigned*)&qplo[(r0 + 8) * PIT + cA];
                al[i][2] = *(const unsigned*)&qplo[r0 * PIT + cA + 8];
                al[i][3] = *(const unsigned*)&qplo[(r0 + 8) * PIT + cA + 8];
            }
            #pragma unroll
            for (int j = 0; j < 2; j++) {
                int er = warp_n * 16 + j * 8 + g;
                unsigned b0 = *(const unsigned*)&cthi[er * PIT + cA];
                unsigned b1 = *(const unsigned*)&cthi[er * PIT + cA + 8];
                unsigned l0 = *(const unsigned*)&ctlo[er * PIT + cA];
                unsigned l1 = *(const unsigned*)&ctlo[er * PIT + cA + 8];
                #pragma unroll
                for (int i = 0; i < 2; i++) {
                    mma16816(c2[i][j], ah[i][0], ah[i][1], ah[i][2], ah[i][3], b0, b1);
                    mma16816(c2[i][j], ah[i][0], ah[i][1], ah[i][2], ah[i][3], l0, l1);
                    mma16816(c2[i][j], al[i][0], al[i][1], al[i][2], al[i][3], b0, b1);
                }
            }
        }
    }

    // epilogue: scale by 1/D and store
    #pragma unroll
    for (int i = 0; i < 2; i++) {
        int row = warp_m * 32 + i * 16 + g;
        float dv0 = dinv[row], dv1 = dinv[row + 8];
        #pragma unroll
        for (int j = 0; j < 2; j++) {
            int e = warp_n * 16 + j * 8 + 2 * tig;
            float2 v0 = make_float2(c2[i][j][0] * dv0, c2[i][j][1] * dv0);
            float2 v1 = make_float2(c2[i][j][2] * dv1, c2[i][j][3] * dv1);
            *(float2*)(out + ((size_t)bh * Nn + n0 + row) * Ee + e) = v0;
            *(float2*)(out + ((size_t)bh * Nn + n0 + row + 8) * Ee + e) = v1;
        }
    }
}

// ============================================================
extern "C" void kernel_launch(void* const* d_in, const int* in_sizes, int n_in,
                              void* d_out, int out_size)
{
    const float* q = (const float*)d_in[0];
    const float* k = (const float*)d_in[1];
    const float* v = (const float*)d_in[2];
    const float* p = (const float*)d_in[3];
    float* out = (float*)d_out;

    cudaFuncSetAttribute(kdash_kernel, cudaFuncAttributeMaxDynamicSharedMemorySize,
                         (int)KD_SMEM);
    cudaFuncSetAttribute(kq_kernel, cudaFuncAttributeMaxDynamicSharedMemorySize,
                         (int)KQ_SMEM);

    psplit_kernel<<<64, 256>>>(p);
    init_kernel<<<1, 1>>>();
    kdash_kernel<<<dim3(Nn / 128, Mm / 128, BH), 256, KD_SMEM>>>(k);
    kctx_kernel<<<dim3(NS, BH), 256>>>(v);
    {
        const int CT = BH * Ee * Mm;
        reduce_kernel<<<(CT + BH * Mm + 255) / 256, 256>>>();
    }
    kq_kernel<<<dim3(Nn / 64, BH), 256, KQ_SMEM>>>(q, out);
    (void)in_sizes; (void)n_in; (void)out_size;
}